// round 11
// baseline (speedup 1.0000x reference)
#include <cuda_runtime.h>

// XY model log-density: out[s] = sum_i cos(x[up(i)] - x[i]) + cos(x[right(i)] - x[i])
// 64x64 lattice (4096 sites), 16384 samples, BETA = 1.
//
// R11: R8's exact loop body, but 128 threads/CTA x 8 chunks/thread.
// Trend: 2 chunks/thread = 49.2us, 4 = 43.5us -> test 8. Longer per-warp
// load stream (16 LDG.128) raises MLP_eff; regs stay ~30 (only a,b live).

#define LATTICE 4096
#define THREADS 128

// FMA-pipe cos for d in (-2pi,2pi): half-angle + even Taylor, err <= 4e-6.
__device__ __forceinline__ float cos_poly(float d)
{
    const float y = 0.5f * d;
    const float u = y * y;
    float p = -1.1470746e-11f;
    p = fmaf(p, u,  2.0876757e-9f);
    p = fmaf(p, u, -2.7557319e-7f);
    p = fmaf(p, u,  2.4801587e-5f);
    p = fmaf(p, u, -1.3888889e-3f);
    p = fmaf(p, u,  4.1666668e-2f);
    p = fmaf(p, u, -0.5f);
    p = fmaf(p, u,  1.0f);              // p = cos(y)
    return fmaf(p + p, p, -1.0f);       // 2p^2 - 1
}

__global__ __launch_bounds__(THREADS) void xy_hamiltonian_kernel(
    const float* __restrict__ state,
    float* __restrict__ out)
{
    __shared__ float warp_sums[THREADS / 32];

    const int tid  = threadIdx.x;
    const int lane = tid & 31;
    const float4* __restrict__ rp4 =
        reinterpret_cast<const float4*>(state + (size_t)blockIdx.x * LATTICE);

    // Right-neighbor source lane: within each 16-lane group (one 64-site
    // lattice row = 16 float4), lane L's boundary right-neighbor is lane
    // L+1's a.x, wrapping to the group's first lane at col 63.
    const int src_lane = (lane & ~15) | ((lane + 1) & 15);

    float acc  = 0.0f;
    float accp = 0.0f;
    #pragma unroll
    for (int k = 0; k < 8; k++) {
        const int m = tid + k * THREADS;                           // float4 idx 0..1023
        const float4 a = __ldcs(&rp4[m]);                          // own sites
        const float4 b = __ldcs(&rp4[(m + 16) & (LATTICE/4 - 1)]); // up neighbors (+64, periodic)
        const float xr3 = __shfl_sync(0xffffffffu, a.x, src_lane);

        acc  += __cosf(b.x - a.x);   // up bonds (MUFU)
        acc  += __cosf(b.y - a.y);
        acc  += __cosf(b.z - a.z);
        acc  += __cosf(b.w - a.w);
        acc  += __cosf(a.y - a.x);   // right bonds
        accp += cos_poly(a.z - a.y); // FMA-pipe bond (MUFU relief)
        acc  += __cosf(a.w - a.z);
        acc  += __cosf(xr3 - a.w);
    }
    acc += accp;

    // Warp reduce
    #pragma unroll
    for (int o = 16; o > 0; o >>= 1)
        acc += __shfl_down_sync(0xffffffffu, acc, o);
    if (lane == 0)
        warp_sums[tid >> 5] = acc;
    __syncthreads();

    // Final reduce across 4 warps
    if (tid < 4) {
        float v = warp_sums[tid];
        v += __shfl_down_sync(0x0000000fu, v, 2);
        v += __shfl_down_sync(0x0000000fu, v, 1);
        if (tid == 0)
            out[blockIdx.x] = v;
    }
}

extern "C" void kernel_launch(void* const* d_in, const int* in_sizes, int n_in,
                              void* d_out, int out_size)
{
    const float* state = (const float*)d_in[0];
    // d_in[1] (shift table, int64) is reproduced arithmetically in-kernel.
    float* out = (float*)d_out;

    const int n_samples = in_sizes[0] / LATTICE;  // 16384
    xy_hamiltonian_kernel<<<n_samples, THREADS>>>(state, out);
}

// round 12
// speedup vs baseline: 1.2406x; 1.2406x over previous
#include <cuda_runtime.h>

// XY model log-density: out[s] = sum_i cos(x[up(i)] - x[i]) + cos(x[right(i)] - x[i])
// 64x64 lattice (4096 sites), 16384 samples, BETA = 1.
//
// FINAL (R8 config, best of 11 rounds: 43.5us, ~98% of achieved-HBM roofline).
// - one CTA per sample row; 256 threads x 4 float4 chunks
// - own sites + up-neighbors via LDG.128 evict-first; neighbor indices
//   computed arithmetically (identical to the reference shift table)
// - right bonds from registers + one SHFL.IDX per chunk (wrap-aware)
// - 1 of 8 bonds on the FMA pipe (half-angle Taylor, err <= 4e-6) to
//   relieve MUFU; warp-shuffle + smem block reduction.
// Measured: DRAM 6.4 TB/s, traffic == unique bytes -> bandwidth-floor bound.

#define LATTICE 4096
#define THREADS 256

// FMA-pipe cos for d in (-2pi,2pi): half-angle + even Taylor, err <= 4e-6.
__device__ __forceinline__ float cos_poly(float d)
{
    const float y = 0.5f * d;
    const float u = y * y;
    float p = -1.1470746e-11f;
    p = fmaf(p, u,  2.0876757e-9f);
    p = fmaf(p, u, -2.7557319e-7f);
    p = fmaf(p, u,  2.4801587e-5f);
    p = fmaf(p, u, -1.3888889e-3f);
    p = fmaf(p, u,  4.1666668e-2f);
    p = fmaf(p, u, -0.5f);
    p = fmaf(p, u,  1.0f);              // p = cos(y)
    return fmaf(p + p, p, -1.0f);       // 2p^2 - 1
}

__global__ __launch_bounds__(THREADS) void xy_hamiltonian_kernel(
    const float* __restrict__ state,
    float* __restrict__ out)
{
    __shared__ float warp_sums[THREADS / 32];

    const int tid  = threadIdx.x;
    const int lane = tid & 31;
    const float4* __restrict__ rp4 =
        reinterpret_cast<const float4*>(state + (size_t)blockIdx.x * LATTICE);

    // Right-neighbor source lane: within each 16-lane group (one 64-site
    // lattice row = 16 float4), lane L's boundary right-neighbor is lane
    // L+1's a.x, wrapping to the group's first lane at col 63.
    const int src_lane = (lane & ~15) | ((lane + 1) & 15);

    float acc  = 0.0f;   // MUFU-side accumulator
    float accp = 0.0f;   // poly-side accumulator (independent chain)
    #pragma unroll
    for (int k = 0; k < 4; k++) {
        const int m = tid + k * THREADS;                           // float4 idx 0..1023
        const float4 a = __ldcs(&rp4[m]);                          // own sites
        const float4 b = __ldcs(&rp4[(m + 16) & (LATTICE/4 - 1)]); // up neighbors (+64, periodic)
        const float xr3 = __shfl_sync(0xffffffffu, a.x, src_lane);

        acc  += __cosf(b.x - a.x);   // up bonds (MUFU)
        acc  += __cosf(b.y - a.y);
        acc  += __cosf(b.z - a.z);
        acc  += __cosf(b.w - a.w);
        acc  += __cosf(a.y - a.x);   // right bonds
        accp += cos_poly(a.z - a.y); // FMA-pipe bond (MUFU relief)
        acc  += __cosf(a.w - a.z);
        acc  += __cosf(xr3 - a.w);
    }
    acc += accp;

    // Warp reduce
    #pragma unroll
    for (int o = 16; o > 0; o >>= 1)
        acc += __shfl_down_sync(0xffffffffu, acc, o);
    if (lane == 0)
        warp_sums[tid >> 5] = acc;
    __syncthreads();

    // Final reduce across 8 warps
    if (tid < 8) {
        float v = warp_sums[tid];
        #pragma unroll
        for (int o = 4; o > 0; o >>= 1)
            v += __shfl_down_sync(0x000000ffu, v, o);
        if (tid == 0)
            out[blockIdx.x] = v;
    }
}

extern "C" void kernel_launch(void* const* d_in, const int* in_sizes, int n_in,
                              void* d_out, int out_size)
{
    const float* state = (const float*)d_in[0];
    // d_in[1] (shift table, int64) is reproduced arithmetically in-kernel.
    float* out = (float*)d_out;

    const int n_samples = in_sizes[0] / LATTICE;  // 16384
    xy_hamiltonian_kernel<<<n_samples, THREADS>>>(state, out);
}

// round 13
// speedup vs baseline: 1.2939x; 1.0430x over previous
#include <cuda_runtime.h>

// XY model log-density: out[s] = sum_i cos(x[up(i)] - x[i]) + cos(x[right(i)] - x[i])
// 64x64 lattice (4096 sites), 16384 samples, BETA = 1.
//
// R13: chained-chunk variant of the best kernel (43.5us). Thread t owns the
// chunk chain {start, start+16, start+32, start+48} (stride = one lattice
// row), so each chunk's up-neighbor IS the next chunk in the chain: the
// b-load of iteration j is reused as the a of iteration j+1.
// Loads/thread: 8 -> 5 (-37.5% L1/L2 requests), zero added issue work.
// start = (tid>>4)*64 + (tid&15): every warp LDG still touches 4x128B lines.

#define LATTICE 4096
#define THREADS 256

// FMA-pipe cos for d in (-2pi,2pi): half-angle + even Taylor, err <= 4e-6.
__device__ __forceinline__ float cos_poly(float d)
{
    const float y = 0.5f * d;
    const float u = y * y;
    float p = -1.1470746e-11f;
    p = fmaf(p, u,  2.0876757e-9f);
    p = fmaf(p, u, -2.7557319e-7f);
    p = fmaf(p, u,  2.4801587e-5f);
    p = fmaf(p, u, -1.3888889e-3f);
    p = fmaf(p, u,  4.1666668e-2f);
    p = fmaf(p, u, -0.5f);
    p = fmaf(p, u,  1.0f);              // p = cos(y)
    return fmaf(p + p, p, -1.0f);       // 2p^2 - 1
}

__global__ __launch_bounds__(THREADS) void xy_hamiltonian_kernel(
    const float* __restrict__ state,
    float* __restrict__ out)
{
    __shared__ float warp_sums[THREADS / 32];

    const int tid  = threadIdx.x;
    const int lane = tid & 31;
    const float4* __restrict__ rp4 =
        reinterpret_cast<const float4*>(state + (size_t)blockIdx.x * LATTICE);

    // Chain start: chunks with (m mod 64) < 16. Lanes 0-15 of a warp cover
    // 16 consecutive chunks of one lattice row; lanes 16-31 the next group.
    const int start = ((tid >> 4) << 6) + (tid & 15);

    // Right-neighbor source lane: within each 16-lane group, lane L's
    // boundary right-neighbor is lane L+1's cur.x, wrapping at col 63.
    const int src_lane = (lane & ~15) | ((lane + 1) & 15);

    float4 cur = __ldcs(&rp4[start]);

    float acc  = 0.0f;   // MUFU-side accumulator
    float accp = 0.0f;   // poly-side accumulator (independent chain)
    #pragma unroll
    for (int j = 0; j < 4; j++) {
        // Up-neighbor chunk = next chunk in this thread's chain.
        const float4 nxt = __ldcs(&rp4[(start + 16 * (j + 1)) & (LATTICE/4 - 1)]);
        const float xr3 = __shfl_sync(0xffffffffu, cur.x, src_lane);

        acc  += __cosf(nxt.x - cur.x);   // up bonds (MUFU)
        acc  += __cosf(nxt.y - cur.y);
        acc  += __cosf(nxt.z - cur.z);
        acc  += __cosf(nxt.w - cur.w);
        acc  += __cosf(cur.y - cur.x);   // right bonds
        accp += cos_poly(cur.z - cur.y); // FMA-pipe bond (MUFU relief)
        acc  += __cosf(cur.w - cur.z);
        acc  += __cosf(xr3   - cur.w);

        cur = nxt;
    }
    acc += accp;

    // Warp reduce
    #pragma unroll
    for (int o = 16; o > 0; o >>= 1)
        acc += __shfl_down_sync(0xffffffffu, acc, o);
    if (lane == 0)
        warp_sums[tid >> 5] = acc;
    __syncthreads();

    // Final reduce across 8 warps
    if (tid < 8) {
        float v = warp_sums[tid];
        #pragma unroll
        for (int o = 4; o > 0; o >>= 1)
            v += __shfl_down_sync(0x000000ffu, v, o);
        if (tid == 0)
            out[blockIdx.x] = v;
    }
}

extern "C" void kernel_launch(void* const* d_in, const int* in_sizes, int n_in,
                              void* d_out, int out_size)
{
    const float* state = (const float*)d_in[0];
    // d_in[1] (shift table, int64) is reproduced arithmetically in-kernel.
    float* out = (float*)d_out;

    const int n_samples = in_sizes[0] / LATTICE;  // 16384
    xy_hamiltonian_kernel<<<n_samples, THREADS>>>(state, out);
}